// round 7
// baseline (speedup 1.0000x reference)
#include <cuda_runtime.h>
#include <cuda_bf16.h>
#include <math.h>

// ---------------- problem constants ----------------
#define Dd   128
#define DM   256
#define DI   512
#define Hh   512
#define KNN  10
#define NN   64
#define BQ   4096
#define BS   128
#define G4   2048   // 4*H

// ---------------- scratch (device globals; allocation-free) ----------------
__device__ __align__(16) float g_qnb [BQ*DM];
__device__ __align__(16) float g_snb [BS*DM];
__device__ __align__(16) float g_h1q [BQ*DI];
__device__ __align__(16) float g_ffnq[BQ*DM];
__device__ __align__(16) float g_qg  [BQ*DM];
__device__ __align__(16) float g_h1s [BS*DI];
__device__ __align__(16) float g_ffns[BS*DM];
__device__ __align__(16) float g_senc[BS*DM];
__device__ __align__(16) float g_sg  [DM];
__device__ __align__(16) float g_sgpart[G4];
__device__ __align__(16) float g_bsum [G4];
__device__ __align__(16) float g_base [BQ*G4];
__device__ __align__(16) float g_gates[BQ*G4];
__device__ __align__(16) float g_c   [BQ*Hh];
__device__ __align__(16) float g_h   [BQ*DM];
__device__ float g_sgnorm;

__device__ __forceinline__ float sigm(float x){ return 1.0f/(1.0f+expf(-x)); }

// ---------------- neighbor encoder ----------------
// one block (256 thr) per row. dstSel: 0 -> g_qnb, 1 -> g_snb. sideOff: 0 or 128.
__global__ void k_neighbor(const int* __restrict__ conn, const int* __restrict__ pairs, int col,
                           const float* __restrict__ emb,
                           const float* __restrict__ W, const float* __restrict__ wb,
                           const float* __restrict__ gb,
                           int dstSel, int sideOff)
{
    __shared__ __align__(16) float cen[Dd];
    __shared__ float ents[NN][Dd];
    __shared__ float sims[NN];
    __shared__ int   sel[KNN];
    __shared__ __align__(16) float avg[DM];

    int b    = blockIdx.x;
    int tid  = threadIdx.x;
    int lane = tid & 31;
    int w    = tid >> 5;

    int id = pairs[b*2 + col];
    if (tid < Dd) cen[tid] = emb[(size_t)id*Dd + tid];
    __syncthreads();

    // per-warp center norm (redundant per warp, cheap)
    float cs = 0.f;
    #pragma unroll
    for (int j = 0; j < 4; j++){ float v = cen[lane + 32*j]; cs += v*v; }
    #pragma unroll
    for (int off = 16; off; off >>= 1) cs += __shfl_xor_sync(0xffffffffu, cs, off);
    float cn = fmaxf(sqrtf(cs), 1e-8f);

    // 8 warps x 8 neighbors: gather ent, sim
    for (int q = 0; q < 8; q++){
        int n   = w*8 + q;
        int eid = conn[((size_t)b*NN + n)*2 + 1];
        float dot = 0.f, sq = 0.f;
        #pragma unroll
        for (int j = 0; j < 4; j++){
            float e = emb[(size_t)eid*Dd + lane + 32*j];
            ents[n][lane + 32*j] = e;
            dot += e * cen[lane + 32*j];
            sq  += e * e;
        }
        #pragma unroll
        for (int off = 16; off; off >>= 1){
            dot += __shfl_xor_sync(0xffffffffu, dot, off);
            sq  += __shfl_xor_sync(0xffffffffu, sq , off);
        }
        if (lane == 0) sims[n] = dot / (cn * fmaxf(sqrtf(sq), 1e-8f));
    }
    __syncthreads();

    // stable top-10 (lowest index wins ties -> matches jax.lax.top_k set)
    if (tid == 0){
        float local[NN];
        for (int n = 0; n < NN; n++) local[n] = sims[n];
        for (int k = 0; k < KNN; k++){
            int bi = 0; float bv = local[0];
            for (int n = 1; n < NN; n++){ if (local[n] > bv){ bv = local[n]; bi = n; } }
            sel[k] = bi; local[bi] = -1e30f;
        }
    }
    __syncthreads();

    // average selected [rel ; ent]
    if (tid < Dd){
        float se = 0.f, sr = 0.f;
        for (int k = 0; k < KNN; k++){
            int n = sel[k];
            se += ents[n][tid];
            int rid = conn[((size_t)b*NN + n)*2 + 0];
            sr += emb[(size_t)rid*Dd + tid];
        }
        avg[tid]      = sr * 0.1f;
        avg[Dd + tid] = se * 0.1f;
    }
    __syncthreads();

    // out[d] = tanh(avg . W[d,:] + wb[d] + gb[d])
    if (tid < Dd){
        float o = wb[tid] + gb[tid];
        const float4* wr = (const float4*)(W + (size_t)tid*DM);
        const float4* av = (const float4*)avg;
        #pragma unroll 8
        for (int f = 0; f < DM/4; f++){
            float4 w4 = wr[f]; float4 a4 = av[f];
            o += w4.x*a4.x + w4.y*a4.y + w4.z*a4.z + w4.w*a4.w;
        }
        float* dst = dstSel ? g_snb : g_qnb;
        dst[(size_t)b*DM + sideOff + tid] = tanhf(o);
    }
}

// ---------------- generic fp32 GEMM: C[M,N] = op(A[M,K] @ W[N,K]^T + bias[n] (+ add)) ----
// BM=128, BN=64, BK=16, 256 threads, 8x4 per thread. All dims divide tiles exactly.
__global__ __launch_bounds__(256) void k_gemm(int mode,
                                              const float* __restrict__ Wext,
                                              const float* __restrict__ biasExt)
{
    const float* A; const float* W; const float* bias; const float* add = nullptr;
    float* C; int lda, ldw, ldc, K, ldadd = 0; int relu = 0, hasAdd = 0;
    switch (mode){
      case 0: A=g_snb; lda=DM;  W=Wext; ldw=DM; bias=biasExt;  C=g_h1s;  ldc=DI; K=DM; relu=1; break;
      case 1: A=g_h1s; lda=DI;  W=Wext; ldw=DI; bias=biasExt;  C=g_ffns; ldc=DM; K=DI;          break;
      case 2: A=g_qnb; lda=DM;  W=Wext; ldw=DM; bias=biasExt;  C=g_h1q;  ldc=DI; K=DM; relu=1; break;
      case 3: A=g_h1q; lda=DI;  W=Wext; ldw=DI; bias=biasExt;  C=g_ffnq; ldc=DM; K=DI;          break;
      case 4: A=g_qg;  lda=DM;  W=Wext; ldw=DM; bias=g_bsum;   C=g_base; ldc=G4; K=DM;          break;
      default:A=g_h;   lda=DM;  W=Wext; ldw=Hh; bias=g_sgpart; C=g_gates;ldc=G4; K=DM;
              add=g_base; ldadd=G4; hasAdd=1; break;
    }

    __shared__ __align__(16) float As[16][132];
    __shared__ __align__(16) float Ws[16][68];

    int tid = threadIdx.x;
    int m0 = blockIdx.y * 128, n0 = blockIdx.x * 64;
    int tx = tid & 15, ty = tid >> 4;
    int lm = tid >> 2, lk = (tid & 3) * 4;

    float acc[8][4];
    #pragma unroll
    for (int i = 0; i < 8; i++)
        #pragma unroll
        for (int j = 0; j < 4; j++) acc[i][j] = 0.f;

    for (int k0 = 0; k0 < K; k0 += 16){
        #pragma unroll
        for (int r = 0; r < 2; r++){
            int m = lm + r*64;
            float4 v = *(const float4*)&A[(size_t)(m0+m)*lda + k0 + lk];
            As[lk+0][m] = v.x; As[lk+1][m] = v.y; As[lk+2][m] = v.z; As[lk+3][m] = v.w;
        }
        {
            float4 u = *(const float4*)&W[(size_t)(n0+lm)*ldw + k0 + lk];
            Ws[lk+0][lm] = u.x; Ws[lk+1][lm] = u.y; Ws[lk+2][lm] = u.z; Ws[lk+3][lm] = u.w;
        }
        __syncthreads();
        #pragma unroll
        for (int k = 0; k < 16; k++){
            float4 a0 = *(const float4*)&As[k][ty*8];
            float4 a1 = *(const float4*)&As[k][ty*8+4];
            float4 b0 = *(const float4*)&Ws[k][tx*4];
            float a[8] = {a0.x,a0.y,a0.z,a0.w,a1.x,a1.y,a1.z,a1.w};
            float bb[4] = {b0.x,b0.y,b0.z,b0.w};
            #pragma unroll
            for (int i = 0; i < 8; i++)
                #pragma unroll
                for (int j = 0; j < 4; j++) acc[i][j] += a[i]*bb[j];
        }
        __syncthreads();
    }

    int n = n0 + tx*4;
    float4 bv = *(const float4*)&bias[n];
    #pragma unroll
    for (int i = 0; i < 8; i++){
        int m = m0 + ty*8 + i;
        float4 av = make_float4(0.f,0.f,0.f,0.f);
        if (hasAdd) av = *(const float4*)&add[(size_t)m*ldadd + n];
        float4 o;
        o.x = acc[i][0] + bv.x + av.x;
        o.y = acc[i][1] + bv.y + av.y;
        o.z = acc[i][2] + bv.z + av.z;
        o.w = acc[i][3] + bv.w + av.w;
        if (relu){
            o.x = fmaxf(o.x,0.f); o.y = fmaxf(o.y,0.f);
            o.z = fmaxf(o.z,0.f); o.w = fmaxf(o.w,0.f);
        }
        *(float4*)&C[(size_t)m*ldc + n] = o;
    }
}

// ---------------- residual LayerNorm: y = LN(ffn + x)*g + b, one warp per row ------
__global__ void k_ln(int mode, const float* __restrict__ g, const float* __restrict__ bb, int B)
{
    int warp = (blockIdx.x * blockDim.x + threadIdx.x) >> 5;
    int lane = threadIdx.x & 31;
    if (warp >= B) return;
    const float* ffn = mode ? g_ffnq : g_ffns;
    const float* x   = mode ? g_qnb  : g_snb;
    float*       y   = mode ? g_qg   : g_senc;

    float v[8]; float s = 0.f;
    #pragma unroll
    for (int j = 0; j < 8; j++){
        size_t idx = (size_t)warp*DM + lane + 32*j;
        v[j] = ffn[idx] + x[idx];
        s += v[j];
    }
    #pragma unroll
    for (int off = 16; off; off >>= 1) s += __shfl_xor_sync(0xffffffffu, s, off);
    float mu = s * (1.0f/DM);
    float q = 0.f;
    #pragma unroll
    for (int j = 0; j < 8; j++){ float d = v[j]-mu; q += d*d; }
    #pragma unroll
    for (int off = 16; off; off >>= 1) q += __shfl_xor_sync(0xffffffffu, q, off);
    float inv = rsqrtf(q * (1.0f/DM) + 1e-5f);
    #pragma unroll
    for (int j = 0; j < 8; j++){
        int d = lane + 32*j;
        y[(size_t)warp*DM + d] = (v[j]-mu)*inv*g[d] + bb[d];
    }
}

// ---------------- support_g = mean over rows + its norm --------------------
__global__ void k_sg()
{
    int d = threadIdx.x;   // 256 threads
    float s = 0.f;
    for (int r = 0; r < BS; r++) s += g_senc[(size_t)r*DM + d];
    s *= (1.0f/BS);
    g_sg[d] = s;
    __shared__ float red[DM];
    red[d] = s*s;
    __syncthreads();
    for (int o = 128; o; o >>= 1){
        if (d < o) red[d] += red[d+o];
        __syncthreads();
    }
    if (d == 0) g_sgnorm = sqrtf(red[0]);
}

// ---------------- sg_part[j] = sg . W_hh[j, 256:512]; bsum = b_ih + b_hh --------
__global__ void k_sgpart(const float* __restrict__ Whh,
                         const float* __restrict__ bih, const float* __restrict__ bhh)
{
    __shared__ float s[DM];
    if (threadIdx.x < DM) s[threadIdx.x] = g_sg[threadIdx.x];
    __syncthreads();
    int j = blockIdx.x * blockDim.x + threadIdx.x;
    if (j >= G4) return;
    const float* w = Whh + (size_t)j*Hh + DM;
    float acc = 0.f;
    #pragma unroll 8
    for (int d = 0; d < DM; d++) acc += s[d]*w[d];
    g_sgpart[j] = acc;
    g_bsum[j]   = bih[j] + bhh[j];
}

// ---------------- LSTM cell update -----------------------------------------
__global__ void k_cell(int step)
{
    int idx = blockIdx.x * blockDim.x + threadIdx.x;   // < BQ*Hh
    int b = idx >> 9, d = idx & 511;
    const float* gates = (step == 0) ? g_base : g_gates;
    size_t row = (size_t)b * G4;
    float gi = gates[row + d];
    float gf = gates[row + 512 + d];
    float gg = gates[row + 1024 + d];
    float go = gates[row + 1536 + d];
    float cp = (step == 0) ? 0.f : g_c[idx];
    float c  = sigm(gf)*cp + sigm(gi)*tanhf(gg);
    g_c[idx] = c;
    if (d < DM){
        float hn = sigm(go)*tanhf(c);
        g_h[(size_t)b*DM + d] = g_qg[(size_t)b*DM + d] + hn;
    }
}

// ---------------- final cosine vs support_g --------------------------------
__global__ void k_final(float* __restrict__ out)
{
    int warp = (blockIdx.x * blockDim.x + threadIdx.x) >> 5;
    int lane = threadIdx.x & 31;
    if (warp >= BQ) return;
    float dot = 0.f, nn = 0.f;
    #pragma unroll
    for (int j = 0; j < 8; j++){
        int d = lane + 32*j;
        float h = g_h[(size_t)warp*DM + d];
        dot += h * g_sg[d];
        nn  += h * h;
    }
    #pragma unroll
    for (int off = 16; off; off >>= 1){
        dot += __shfl_xor_sync(0xffffffffu, dot, off);
        nn  += __shfl_xor_sync(0xffffffffu, nn , off);
    }
    if (lane == 0)
        out[warp] = dot / (fmaxf(sqrtf(nn), 1e-12f) * fmaxf(g_sgnorm, 1e-12f));
}

// ---------------- launch --------------------------------------------------
extern "C" void kernel_launch(void* const* d_in, const int* in_sizes, int n_in,
                              void* d_out, int out_size)
{
    const int*   query   = (const int*)  d_in[0];
    const int*   support = (const int*)  d_in[1];
    const int*   qlc     = (const int*)  d_in[2];
    const int*   qrc     = (const int*)  d_in[4];
    const int*   slc     = (const int*)  d_in[6];
    const int*   src     = (const int*)  d_in[8];
    const float* emb     = (const float*)d_in[10];
    const float* gcnW    = (const float*)d_in[11];
    const float* gcnwb   = (const float*)d_in[12];
    const float* gcnb    = (const float*)d_in[13];
    const float* sew1    = (const float*)d_in[14];
    const float* seb1    = (const float*)d_in[15];
    const float* sew2    = (const float*)d_in[16];
    const float* seb2    = (const float*)d_in[17];
    const float* lng     = (const float*)d_in[18];
    const float* lnb     = (const float*)d_in[19];
    const float* Wih     = (const float*)d_in[20];
    const float* Whh     = (const float*)d_in[21];
    const float* bih     = (const float*)d_in[22];
    const float* bhh     = (const float*)d_in[23];
    float* out = (float*)d_out;

    // 1) neighbor encoders
    k_neighbor<<<BQ, 256>>>(qlc, query,   0, emb, gcnW, gcnwb, gcnb, 0, 0);
    k_neighbor<<<BQ, 256>>>(qrc, query,   1, emb, gcnW, gcnwb, gcnb, 0, Dd);
    k_neighbor<<<BS, 256>>>(slc, support, 0, emb, gcnW, gcnwb, gcnb, 1, 0);
    k_neighbor<<<BS, 256>>>(src, support, 1, emb, gcnW, gcnwb, gcnb, 1, Dd);

    // 2) support encoder -> support_g, sg_part, bsum
    k_gemm<<<dim3(DI/64, BS/128), 256>>>(0, sew1, seb1);
    k_gemm<<<dim3(DM/64, BS/128), 256>>>(1, sew2, seb2);
    k_ln<<<BS/8, 256>>>(0, lng, lnb, BS);
    k_sg<<<1, 256>>>();
    k_sgpart<<<G4/256, 256>>>(Whh, bih, bhh);

    // 3) query encoder (support encoder on q_nb)
    k_gemm<<<dim3(DI/64, BQ/128), 256>>>(2, sew1, seb1);
    k_gemm<<<dim3(DM/64, BQ/128), 256>>>(3, sew2, seb2);
    k_ln<<<BQ/8, 256>>>(1, lng, lnb, BQ);

    // 4) base = query_g @ W_ih^T + b_ih + b_hh
    k_gemm<<<dim3(G4/64, BQ/128), 256>>>(4, Wih, nullptr);

    // 5) LSTM steps (step0: gates == base since h_r == 0)
    k_cell<<<BQ*Hh/256, 256>>>(0);
    for (int s = 1; s < 4; s++){
        k_gemm<<<dim3(G4/64, BQ/128), 256>>>(5, Whh, nullptr);
        k_cell<<<BQ*Hh/256, 256>>>(s);
    }

    // 6) cosine output
    k_final<<<BQ/8, 256>>>(out);
}

// round 8
// speedup vs baseline: 1.0024x; 1.0024x over previous
#include <cuda_runtime.h>
#include <cuda_bf16.h>
#include <math.h>

// ---------------- problem constants ----------------
#define Dd   128
#define DM   256
#define DI   512
#define Hh   512
#define KNN  10
#define NN   64
#define BQ   4096
#define BS   128
#define G4   2048   // 4*H

// ---------------- scratch (device globals; allocation-free) ----------------
__device__ __align__(16) float g_qnb [BQ*DM];
__device__ __align__(16) float g_snb [BS*DM];
__device__ __align__(16) float g_h1q [BQ*DI];
__device__ __align__(16) float g_ffnq[BQ*DM];
__device__ __align__(16) float g_qg  [BQ*DM];
__device__ __align__(16) float g_h1s [BS*DI];
__device__ __align__(16) float g_ffns[BS*DM];
__device__ __align__(16) float g_senc[BS*DM];
__device__ __align__(16) float g_sg  [DM];
__device__ __align__(16) float g_sgpart[G4];
__device__ __align__(16) float g_bsum [G4];
__device__ __align__(16) float g_base [BQ*G4];
__device__ __align__(16) float g_gates[BQ*G4];
__device__ __align__(16) float g_c   [BQ*Hh];
__device__ __align__(16) float g_h   [BQ*DM];
__device__ float g_sgnorm;

__device__ __forceinline__ float sigm(float x){ return 1.0f/(1.0f+expf(-x)); }

// ---------------- neighbor encoder ----------------
// one block (256 thr) per row. dstSel: 0 -> g_qnb, 1 -> g_snb. sideOff: 0 or 128.
__global__ void k_neighbor(const int* __restrict__ conn, const int* __restrict__ pairs, int col,
                           const float* __restrict__ emb,
                           const float* __restrict__ W, const float* __restrict__ wb,
                           const float* __restrict__ gb,
                           int dstSel, int sideOff)
{
    __shared__ __align__(16) float cen[Dd];
    __shared__ float ents[NN][Dd];
    __shared__ float sims[NN];
    __shared__ int   sel[KNN];
    __shared__ __align__(16) float avg[DM];

    int b    = blockIdx.x;
    int tid  = threadIdx.x;
    int lane = tid & 31;
    int w    = tid >> 5;

    int id = pairs[b*2 + col];
    if (tid < Dd) cen[tid] = emb[(size_t)id*Dd + tid];
    __syncthreads();

    // per-warp center norm (redundant per warp, cheap)
    float cs = 0.f;
    #pragma unroll
    for (int j = 0; j < 4; j++){ float v = cen[lane + 32*j]; cs += v*v; }
    #pragma unroll
    for (int off = 16; off; off >>= 1) cs += __shfl_xor_sync(0xffffffffu, cs, off);
    float cn = fmaxf(sqrtf(cs), 1e-8f);

    // 8 warps x 8 neighbors: gather ent, sim
    for (int q = 0; q < 8; q++){
        int n   = w*8 + q;
        int eid = conn[((size_t)b*NN + n)*2 + 1];
        float dot = 0.f, sq = 0.f;
        #pragma unroll
        for (int j = 0; j < 4; j++){
            float e = emb[(size_t)eid*Dd + lane + 32*j];
            ents[n][lane + 32*j] = e;
            dot += e * cen[lane + 32*j];
            sq  += e * e;
        }
        #pragma unroll
        for (int off = 16; off; off >>= 1){
            dot += __shfl_xor_sync(0xffffffffu, dot, off);
            sq  += __shfl_xor_sync(0xffffffffu, sq , off);
        }
        if (lane == 0) sims[n] = dot / (cn * fmaxf(sqrtf(sq), 1e-8f));
    }
    __syncthreads();

    // stable top-10 (lowest index wins ties -> matches jax.lax.top_k set)
    if (tid == 0){
        float local[NN];
        for (int n = 0; n < NN; n++) local[n] = sims[n];
        for (int k = 0; k < KNN; k++){
            int bi = 0; float bv = local[0];
            for (int n = 1; n < NN; n++){ if (local[n] > bv){ bv = local[n]; bi = n; } }
            sel[k] = bi; local[bi] = -1e30f;
        }
    }
    __syncthreads();

    // average selected [rel ; ent]
    if (tid < Dd){
        float se = 0.f, sr = 0.f;
        for (int k = 0; k < KNN; k++){
            int n = sel[k];
            se += ents[n][tid];
            int rid = conn[((size_t)b*NN + n)*2 + 0];
            sr += emb[(size_t)rid*Dd + tid];
        }
        avg[tid]      = sr * 0.1f;
        avg[Dd + tid] = se * 0.1f;
    }
    __syncthreads();

    // out[d] = tanh(avg . W[d,:] + wb[d] + gb[d])
    if (tid < Dd){
        float o = wb[tid] + gb[tid];
        const float4* wr = (const float4*)(W + (size_t)tid*DM);
        const float4* av = (const float4*)avg;
        #pragma unroll 8
        for (int f = 0; f < DM/4; f++){
            float4 w4 = wr[f]; float4 a4 = av[f];
            o += w4.x*a4.x + w4.y*a4.y + w4.z*a4.z + w4.w*a4.w;
        }
        float* dst = dstSel ? g_snb : g_qnb;
        dst[(size_t)b*DM + sideOff + tid] = tanhf(o);
    }
}

// ---------------- generic fp32 GEMM: C[M,N] = op(A[M,K] @ W[N,K]^T + bias[n] (+ add)) ----
// BM=128, BN=64, BK=16, 256 threads, 8x4 per thread. All dims divide tiles exactly.
__global__ __launch_bounds__(256) void k_gemm(int mode,
                                              const float* __restrict__ Wext,
                                              const float* __restrict__ biasExt)
{
    const float* A; const float* W; const float* bias; const float* add = nullptr;
    float* C; int lda, ldw, ldc, K, ldadd = 0; int relu = 0, hasAdd = 0;
    switch (mode){
      case 0: A=g_snb; lda=DM;  W=Wext; ldw=DM; bias=biasExt;  C=g_h1s;  ldc=DI; K=DM; relu=1; break;
      case 1: A=g_h1s; lda=DI;  W=Wext; ldw=DI; bias=biasExt;  C=g_ffns; ldc=DM; K=DI;          break;
      case 2: A=g_qnb; lda=DM;  W=Wext; ldw=DM; bias=biasExt;  C=g_h1q;  ldc=DI; K=DM; relu=1; break;
      case 3: A=g_h1q; lda=DI;  W=Wext; ldw=DI; bias=biasExt;  C=g_ffnq; ldc=DM; K=DI;          break;
      case 4: A=g_qg;  lda=DM;  W=Wext; ldw=DM; bias=g_bsum;   C=g_base; ldc=G4; K=DM;          break;
      default:A=g_h;   lda=DM;  W=Wext; ldw=Hh; bias=g_sgpart; C=g_gates;ldc=G4; K=DM;
              add=g_base; ldadd=G4; hasAdd=1; break;
    }

    __shared__ __align__(16) float As[16][132];
    __shared__ __align__(16) float Ws[16][68];

    int tid = threadIdx.x;
    int m0 = blockIdx.y * 128, n0 = blockIdx.x * 64;
    int tx = tid & 15, ty = tid >> 4;
    int lm = tid >> 2, lk = (tid & 3) * 4;

    float acc[8][4];
    #pragma unroll
    for (int i = 0; i < 8; i++)
        #pragma unroll
        for (int j = 0; j < 4; j++) acc[i][j] = 0.f;

    for (int k0 = 0; k0 < K; k0 += 16){
        #pragma unroll
        for (int r = 0; r < 2; r++){
            int m = lm + r*64;
            float4 v = *(const float4*)&A[(size_t)(m0+m)*lda + k0 + lk];
            As[lk+0][m] = v.x; As[lk+1][m] = v.y; As[lk+2][m] = v.z; As[lk+3][m] = v.w;
        }
        {
            float4 u = *(const float4*)&W[(size_t)(n0+lm)*ldw + k0 + lk];
            Ws[lk+0][lm] = u.x; Ws[lk+1][lm] = u.y; Ws[lk+2][lm] = u.z; Ws[lk+3][lm] = u.w;
        }
        __syncthreads();
        #pragma unroll
        for (int k = 0; k < 16; k++){
            float4 a0 = *(const float4*)&As[k][ty*8];
            float4 a1 = *(const float4*)&As[k][ty*8+4];
            float4 b0 = *(const float4*)&Ws[k][tx*4];
            float a[8] = {a0.x,a0.y,a0.z,a0.w,a1.x,a1.y,a1.z,a1.w};
            float bb[4] = {b0.x,b0.y,b0.z,b0.w};
            #pragma unroll
            for (int i = 0; i < 8; i++)
                #pragma unroll
                for (int j = 0; j < 4; j++) acc[i][j] += a[i]*bb[j];
        }
        __syncthreads();
    }

    int n = n0 + tx*4;
    float4 bv = *(const float4*)&bias[n];
    #pragma unroll
    for (int i = 0; i < 8; i++){
        int m = m0 + ty*8 + i;
        float4 av = make_float4(0.f,0.f,0.f,0.f);
        if (hasAdd) av = *(const float4*)&add[(size_t)m*ldadd + n];
        float4 o;
        o.x = acc[i][0] + bv.x + av.x;
        o.y = acc[i][1] + bv.y + av.y;
        o.z = acc[i][2] + bv.z + av.z;
        o.w = acc[i][3] + bv.w + av.w;
        if (relu){
            o.x = fmaxf(o.x,0.f); o.y = fmaxf(o.y,0.f);
            o.z = fmaxf(o.z,0.f); o.w = fmaxf(o.w,0.f);
        }
        *(float4*)&C[(size_t)m*ldc + n] = o;
    }
}

// ---------------- residual LayerNorm: y = LN(ffn + x)*g + b, one warp per row ------
__global__ void k_ln(int mode, const float* __restrict__ g, const float* __restrict__ bb, int B)
{
    int warp = (blockIdx.x * blockDim.x + threadIdx.x) >> 5;
    int lane = threadIdx.x & 31;
    if (warp >= B) return;
    const float* ffn = mode ? g_ffnq : g_ffns;
    const float* x   = mode ? g_qnb  : g_snb;
    float*       y   = mode ? g_qg   : g_senc;

    float v[8]; float s = 0.f;
    #pragma unroll
    for (int j = 0; j < 8; j++){
        size_t idx = (size_t)warp*DM + lane + 32*j;
        v[j] = ffn[idx] + x[idx];
        s += v[j];
    }
    #pragma unroll
    for (int off = 16; off; off >>= 1) s += __shfl_xor_sync(0xffffffffu, s, off);
    float mu = s * (1.0f/DM);
    float q = 0.f;
    #pragma unroll
    for (int j = 0; j < 8; j++){ float d = v[j]-mu; q += d*d; }
    #pragma unroll
    for (int off = 16; off; off >>= 1) q += __shfl_xor_sync(0xffffffffu, q, off);
    float inv = rsqrtf(q * (1.0f/DM) + 1e-5f);
    #pragma unroll
    for (int j = 0; j < 8; j++){
        int d = lane + 32*j;
        y[(size_t)warp*DM + d] = (v[j]-mu)*inv*g[d] + bb[d];
    }
}

// ---------------- support_g = mean over rows + its norm --------------------
__global__ void k_sg()
{
    int d = threadIdx.x;   // 256 threads
    float s = 0.f;
    for (int r = 0; r < BS; r++) s += g_senc[(size_t)r*DM + d];
    s *= (1.0f/BS);
    g_sg[d] = s;
    __shared__ float red[DM];
    red[d] = s*s;
    __syncthreads();
    for (int o = 128; o; o >>= 1){
        if (d < o) red[d] += red[d+o];
        __syncthreads();
    }
    if (d == 0) g_sgnorm = sqrtf(red[0]);
}

// ---------------- sg_part[j] = sg . W_hh[j, 256:512]; bsum = b_ih + b_hh --------
__global__ void k_sgpart(const float* __restrict__ Whh,
                         const float* __restrict__ bih, const float* __restrict__ bhh)
{
    __shared__ float s[DM];
    if (threadIdx.x < DM) s[threadIdx.x] = g_sg[threadIdx.x];
    __syncthreads();
    int j = blockIdx.x * blockDim.x + threadIdx.x;
    if (j >= G4) return;
    const float* w = Whh + (size_t)j*Hh + DM;
    float acc = 0.f;
    #pragma unroll 8
    for (int d = 0; d < DM; d++) acc += s[d]*w[d];
    g_sgpart[j] = acc;
    g_bsum[j]   = bih[j] + bhh[j];
}

// ---------------- LSTM cell update -----------------------------------------
__global__ void k_cell(int step)
{
    int idx = blockIdx.x * blockDim.x + threadIdx.x;   // < BQ*Hh
    int b = idx >> 9, d = idx & 511;
    const float* gates = (step == 0) ? g_base : g_gates;
    size_t row = (size_t)b * G4;
    float gi = gates[row + d];
    float gf = gates[row + 512 + d];
    float gg = gates[row + 1024 + d];
    float go = gates[row + 1536 + d];
    float cp = (step == 0) ? 0.f : g_c[idx];
    float c  = sigm(gf)*cp + sigm(gi)*tanhf(gg);
    g_c[idx] = c;
    if (d < DM){
        float hn = sigm(go)*tanhf(c);
        g_h[(size_t)b*DM + d] = g_qg[(size_t)b*DM + d] + hn;
    }
}

// ---------------- final cosine vs support_g --------------------------------
__global__ void k_final(float* __restrict__ out)
{
    int warp = (blockIdx.x * blockDim.x + threadIdx.x) >> 5;
    int lane = threadIdx.x & 31;
    if (warp >= BQ) return;
    float dot = 0.f, nn = 0.f;
    #pragma unroll
    for (int j = 0; j < 8; j++){
        int d = lane + 32*j;
        float h = g_h[(size_t)warp*DM + d];
        dot += h * g_sg[d];
        nn  += h * h;
    }
    #pragma unroll
    for (int off = 16; off; off >>= 1){
        dot += __shfl_xor_sync(0xffffffffu, dot, off);
        nn  += __shfl_xor_sync(0xffffffffu, nn , off);
    }
    if (lane == 0)
        out[warp] = dot / (fmaxf(sqrtf(nn), 1e-12f) * fmaxf(g_sgnorm, 1e-12f));
}

// ---------------- launch --------------------------------------------------
extern "C" void kernel_launch(void* const* d_in, const int* in_sizes, int n_in,
                              void* d_out, int out_size)
{
    const int*   query   = (const int*)  d_in[0];
    const int*   support = (const int*)  d_in[1];
    const int*   qlc     = (const int*)  d_in[2];
    const int*   qrc     = (const int*)  d_in[4];
    const int*   slc     = (const int*)  d_in[6];
    const int*   src     = (const int*)  d_in[8];
    const float* emb     = (const float*)d_in[10];
    const float* gcnW    = (const float*)d_in[11];
    const float* gcnwb   = (const float*)d_in[12];
    const float* gcnb    = (const float*)d_in[13];
    const float* sew1    = (const float*)d_in[14];
    const float* seb1    = (const float*)d_in[15];
    const float* sew2    = (const float*)d_in[16];
    const float* seb2    = (const float*)d_in[17];
    const float* lng     = (const float*)d_in[18];
    const float* lnb     = (const float*)d_in[19];
    const float* Wih     = (const float*)d_in[20];
    const float* Whh     = (const float*)d_in[21];
    const float* bih     = (const float*)d_in[22];
    const float* bhh     = (const float*)d_in[23];
    float* out = (float*)d_out;

    // 1) neighbor encoders
    k_neighbor<<<BQ, 256>>>(qlc, query,   0, emb, gcnW, gcnwb, gcnb, 0, 0);
    k_neighbor<<<BQ, 256>>>(qrc, query,   1, emb, gcnW, gcnwb, gcnb, 0, Dd);
    k_neighbor<<<BS, 256>>>(slc, support, 0, emb, gcnW, gcnwb, gcnb, 1, 0);
    k_neighbor<<<BS, 256>>>(src, support, 1, emb, gcnW, gcnwb, gcnb, 1, Dd);

    // 2) support encoder -> support_g, sg_part, bsum
    k_gemm<<<dim3(DI/64, BS/128), 256>>>(0, sew1, seb1);
    k_gemm<<<dim3(DM/64, BS/128), 256>>>(1, sew2, seb2);
    k_ln<<<BS/8, 256>>>(0, lng, lnb, BS);
    k_sg<<<1, 256>>>();
    k_sgpart<<<G4/256, 256>>>(Whh, bih, bhh);

    // 3) query encoder (support encoder on q_nb)
    k_gemm<<<dim3(DI/64, BQ/128), 256>>>(2, sew1, seb1);
    k_gemm<<<dim3(DM/64, BQ/128), 256>>>(3, sew2, seb2);
    k_ln<<<BQ/8, 256>>>(1, lng, lnb, BQ);

    // 4) base = query_g @ W_ih^T + b_ih + b_hh
    k_gemm<<<dim3(G4/64, BQ/128), 256>>>(4, Wih, nullptr);

    // 5) LSTM steps (step0: gates == base since h_r == 0)
    k_cell<<<BQ*Hh/256, 256>>>(0);
    for (int s = 1; s < 4; s++){
        k_gemm<<<dim3(G4/64, BQ/128), 256>>>(5, Whh, nullptr);
        k_cell<<<BQ*Hh/256, 256>>>(s);
    }

    // 6) cosine output
    k_final<<<BQ/8, 256>>>(out);
}